// round 12
// baseline (speedup 1.0000x reference)
#include <cuda_runtime.h>
#include <cuda_bf16.h>
#include <cstdint>

#define BATCH 128
#define CH    128
#define TTNN  2785280      // BATCH*CH*NN elements
#define NN    170
#define TT    12
#define NP    176          // padded node pitch
#define SCP   172          // score smem pitch (bf16)

static __device__ __align__(16) float    g_xs[BATCH * CH * NP];        // t-reduced x
static __device__ __align__(16) unsigned g_EdB[BATCH * NN * (NP/2)];   // E_d^T bf16 pairs
static __device__ float g_Asum[NN * NN];

// k_gemm1 smem: es bf16-pairs [128][88 u32] + xs f32 [128][88]
#define SMEM_G1 ((11264 + 11264) * 4)                  // 90,112 B -> 2 CTA/SM
// k_adj smem: ed f32 [170][176] + sc bf16 [170][172]
#define SMEM_A  (NN * NP * 4 + NN * SCP * 2)           // 178,160 B

// ------------------------------------------------------- packed f32x2 helpers
typedef unsigned long long u64t;

__device__ __forceinline__ u64t splat2(float v) {
    u64t d; asm("mov.b64 %0, {%1, %1};" : "=l"(d) : "f"(v)); return d;
}
__device__ __forceinline__ u64t splat2u(unsigned v) {
    u64t d; asm("mov.b64 %0, {%1, %1};" : "=l"(d) : "r"(v)); return d;
}
__device__ __forceinline__ void ffma2(u64t& c, u64t a, u64t b) {
    asm("fma.rn.f32x2 %0, %1, %2, %3;" : "=l"(c) : "l"(a), "l"(b), "l"(c));
}
__device__ __forceinline__ void unpack2(float& lo, float& hi, u64t v) {
    asm("mov.b64 {%0, %1}, %2;" : "=f"(lo), "=f"(hi) : "l"(v));
}
__device__ __forceinline__ float tanh_ap(float x) {
    float r; asm("tanh.approx.f32 %0, %1;" : "=f"(r) : "f"(x)); return r;
}
__device__ __forceinline__ float bf_lo(unsigned w) { return __uint_as_float(w << 16); }
__device__ __forceinline__ float bf_hi(unsigned w) { return __uint_as_float(w & 0xFFFF0000u); }
__device__ __forceinline__ unsigned bf_pack(float a, float b) {
    __nv_bfloat162 h = __floats2bfloat162_rn(a, b);
    return *reinterpret_cast<unsigned*>(&h);
}
__device__ __forceinline__ float f4sum(float4 v) {
    return (v.x + v.y) + (v.z + v.w);
}
__device__ __forceinline__ void cp16(unsigned saddr, const void* g) {
    asm volatile("cp.async.cg.shared.global [%0], [%1], 16;" :: "r"(saddr), "l"(g));
}

// -------- K_load: cp.async double-buffered staged t-reduction x -> g_xs
// chunk = 256 elements = 768 contiguous float4; load chunk i+1 while reducing i.
__global__ void __launch_bounds__(256) k_load(const float* __restrict__ x) {
    __shared__ __align__(16) float4 st[2][768];
    const int tid = threadIdx.x;

    // zero the pad columns of g_xs (np in [170,176))
    for (int i = blockIdx.x * 256 + tid; i < BATCH * CH * 6; i += gridDim.x * 256) {
        int bc = i / 6, j = i - bc * 6;
        g_xs[(size_t)bc * NP + NN + j] = 0.0f;
    }

    const int nchunks = TTNN / 256;                    // 10880 exactly
    const float4* xf4 = reinterpret_cast<const float4*>(x);
    int ch = blockIdx.x;
    if (ch >= nchunks) return;

    // prologue: stage chunk ch into buffer 0
    {
        size_t base = (size_t)ch * 768;
        unsigned s = (unsigned)__cvta_generic_to_shared(&st[0][tid]);
        cp16(s,        xf4 + base + tid);
        cp16(s + 4096, xf4 + base + 256 + tid);
        cp16(s + 8192, xf4 + base + 512 + tid);
        asm volatile("cp.async.commit_group;");
    }

    int buf = 0;
    for (; ch < nchunks; ch += gridDim.x) {
        int nxt = ch + gridDim.x;
        if (nxt < nchunks) {                           // prefetch next chunk
            size_t base = (size_t)nxt * 768;
            unsigned s = (unsigned)__cvta_generic_to_shared(&st[buf ^ 1][tid]);
            cp16(s,        xf4 + base + tid);
            cp16(s + 4096, xf4 + base + 256 + tid);
            cp16(s + 8192, xf4 + base + 512 + tid);
            asm volatile("cp.async.commit_group;");
            asm volatile("cp.async.wait_group 1;");    // current chunk arrived
        } else {
            asm volatile("cp.async.wait_group 0;");
        }
        __syncthreads();

        // reduce 12-float group for this thread's element
        const float4* p = reinterpret_cast<const float4*>(
            reinterpret_cast<const float*>(st[buf]) + tid * TT);
        float4 v0 = p[0], v1 = p[1], v2 = p[2];
        float s = f4sum(v0) + f4sum(v1) + f4sum(v2);
        int e = ch * 256 + tid;
        int bc = e / NN, n = e - bc * NN;
        g_xs[(size_t)bc * NP + n] = s;

        __syncthreads();                               // all reads of st[buf] done
        buf ^= 1;
    }
}

// --------------- K_gemm1: ed[m][n] = tanh(sum_c Es[c][m] * xs[c][n])  (8x8)
__global__ void __launch_bounds__(256, 2) k_gemm1(const float* __restrict__ Es) {
    extern __shared__ float smf[];
    unsigned* es = reinterpret_cast<unsigned*>(smf);   // bf16x2 [128][88]
    float* xs = smf + CH * 88;                         // f32 [128][88]
    const int tid = threadIdx.x;
    const int b = blockIdx.x, h = blockIdx.y;

    for (int i = tid; i < CH * 88; i += 256) {
        int c = i / 88, mp = i - c * 88;
        int m0 = mp * 2;
        float f0 = 0.f, f1 = 0.f;
        if (m0 < NN) {
            float2 e = *reinterpret_cast<const float2*>(Es + c * NN + m0);
            f0 = e.x; f1 = e.y;
        }
        es[i] = bf_pack(f0, f1);
    }
    {
        const float* src = g_xs + (size_t)b * CH * NP + 88 * h;
        for (int i = tid; i < CH * 22; i += 256) {
            int c = i / 22, q = i - c * 22;
            reinterpret_cast<float4*>(xs)[c * 22 + q] =
                *reinterpret_cast<const float4*>(src + (size_t)c * NP + q * 4);
        }
    }
    __syncthreads();

    const int cell = tid;
    if (cell < 242) {
        const int smi = cell / 11, snj = cell - smi * 11;
        const int am = smi * 8, bn = snj * 8;
        u64t acc[8][4];
        #pragma unroll
        for (int i = 0; i < 8; i++)
            #pragma unroll
            for (int j = 0; j < 4; j++) acc[i][j] = 0ull;

        const unsigned* ep = es + (am >> 1);
        const float* bp = xs + bn;
        #pragma unroll 2
        for (int c = 0; c < CH; c++) {
            uint4 ev = *reinterpret_cast<const uint4*>(ep + c * 88);
            ulonglong2 b01 = *reinterpret_cast<const ulonglong2*>(bp + c * 88);
            ulonglong2 b23 = *reinterpret_cast<const ulonglong2*>(bp + c * 88 + 4);
            unsigned ew[4] = {ev.x, ev.y, ev.z, ev.w};
            #pragma unroll
            for (int q = 0; q < 4; q++) {
                u64t s0 = splat2u(ew[q] << 16);
                u64t s1 = splat2u(ew[q] & 0xFFFF0000u);
                ffma2(acc[2*q][0], s0, b01.x);  ffma2(acc[2*q][1], s0, b01.y);
                ffma2(acc[2*q][2], s0, b23.x);  ffma2(acc[2*q][3], s0, b23.y);
                ffma2(acc[2*q+1][0], s1, b01.x); ffma2(acc[2*q+1][1], s1, b01.y);
                ffma2(acc[2*q+1][2], s1, b23.x); ffma2(acc[2*q+1][3], s1, b23.y);
            }
        }

        #pragma unroll
        for (int mi = 0; mi < 8; mi++) {
            int m = am + mi;
            if (m < NN) {
                float f[8];
                #pragma unroll
                for (int j = 0; j < 4; j++) unpack2(f[2*j], f[2*j+1], acc[mi][j]);
                uint4 o;
                o.x = bf_pack(tanh_ap(f[0]), tanh_ap(f[1]));
                o.y = bf_pack(tanh_ap(f[2]), tanh_ap(f[3]));
                o.z = bf_pack(tanh_ap(f[4]), tanh_ap(f[5]));
                o.w = bf_pack(tanh_ap(f[6]), tanh_ap(f[7]));
                unsigned* dst = g_EdB + ((size_t)b * NN + m) * (NP/2) + ((88*h + bn) >> 1);
                *reinterpret_cast<uint4*>(dst) = o;
            }
        }
    }
}

// -------- K_adj: symmetric GEMM2 (8x8 triangle) + softmax + atomic accumulate
__global__ void __launch_bounds__(512, 1) k_adj() {
    extern __shared__ float sm[];
    float* ed = sm;                                          // [170][176] f32
    __nv_bfloat16* sc = reinterpret_cast<__nv_bfloat16*>(sm + NN * NP);
    const int tid = threadIdx.x;
    const int b = blockIdx.x;

    // copy-in: bf16 -> f32 expansion
    {
        const uint4* src = reinterpret_cast<const uint4*>(g_EdB + (size_t)b * NN * (NP/2));
        for (int i = tid; i < (NN * NP) / 8; i += 512) {
            uint4 v = src[i];
            float4 f0, f1;
            f0.x = bf_lo(v.x); f0.y = bf_hi(v.x); f0.z = bf_lo(v.y); f0.w = bf_hi(v.y);
            f1.x = bf_lo(v.z); f1.y = bf_hi(v.z); f1.z = bf_lo(v.w); f1.w = bf_hi(v.w);
            reinterpret_cast<float4*>(ed)[2*i]   = f0;
            reinterpret_cast<float4*>(ed)[2*i+1] = f1;
        }
    }
    __syncthreads();

    const float scale = 0.08838834764831843f;                // 1/sqrt(128)
    const int cell = tid;
    if (cell < 253) {
        int si = (int)((sqrtf(8.0f * (float)cell + 1.0f) - 1.0f) * 0.5f);
        while ((si + 1) * (si + 2) / 2 <= cell) si++;
        while (si * (si + 1) / 2 > cell) si--;
        const int sj = cell - si * (si + 1) / 2;
        const int n = si * 8, k = sj * 8;

        u64t acc[8][4];
        #pragma unroll
        for (int i = 0; i < 8; i++)
            #pragma unroll
            for (int j = 0; j < 4; j++) acc[i][j] = 0ull;

        #pragma unroll 2
        for (int m = 0; m < NN; m++) {
            const float* row = ed + m * NP;
            ulonglong2 a01 = *reinterpret_cast<const ulonglong2*>(row + n);
            ulonglong2 a23 = *reinterpret_cast<const ulonglong2*>(row + n + 4);
            float4 k0 = *reinterpret_cast<const float4*>(row + k);
            float4 k1 = *reinterpret_cast<const float4*>(row + k + 4);
            float kv[8] = {k0.x, k0.y, k0.z, k0.w, k1.x, k1.y, k1.z, k1.w};
            #pragma unroll
            for (int ki = 0; ki < 8; ki++) {
                u64t s = splat2(kv[ki]);
                ffma2(acc[ki][0], s, a01.x); ffma2(acc[ki][1], s, a01.y);
                ffma2(acc[ki][2], s, a23.x); ffma2(acc[ki][3], s, a23.y);
            }
        }

        #pragma unroll
        for (int ki = 0; ki < 8; ki++) {
            int kk = k + ki;
            if (kk >= NN) continue;
            #pragma unroll
            for (int j = 0; j < 4; j++) {
                float v0, v1;
                unpack2(v0, v1, acc[ki][j]);
                int n0 = n + 2 * j, n1 = n0 + 1;
                __nv_bfloat16 h0 = __float2bfloat16(fmaxf(0.0f, v0 * scale));
                __nv_bfloat16 h1 = __float2bfloat16(fmaxf(0.0f, v1 * scale));
                if (n0 < NN) { sc[n0 * SCP + kk] = h0; sc[kk * SCP + n0] = h0; }
                if (n1 < NN) { sc[n1 * SCP + kk] = h1; sc[kk * SCP + n1] = h1; }
            }
        }
    }
    __syncthreads();

    // row softmax (scores in [0,~15.1] -> no max pass) + atomic accumulate
    const int wid = tid >> 5, lane = tid & 31;
    for (int n = wid; n < NN; n += 16) {
        const __nv_bfloat16* row = sc + n * SCP;
        float ssum = 0.0f;
        for (int kq = lane; kq < NN; kq += 32)
            ssum += __expf(__bfloat162float(row[kq]));
        #pragma unroll
        for (int o = 16; o; o >>= 1)
            ssum += __shfl_xor_sync(0xffffffffu, ssum, o);
        float inv = 1.0f / ssum;
        for (int kq = lane; kq < NN; kq += 32)
            atomicAdd(&g_Asum[n * NN + kq],
                      __expf(__bfloat162float(row[kq])) * inv);
    }
}

// --------------------------------- K_thresh: threshold + self-restore g_Asum
__global__ void k_thresh(float* __restrict__ out) {
    int i = blockIdx.x * blockDim.x + threadIdx.x;
    if (i < NN * NN) {
        out[i] = (g_Asum[i] > 64.0f) ? 1.0f : 0.0f;          // mean > 0.5
        g_Asum[i] = 0.0f;                                    // restore for replay
    }
}

// ------------------------------------------------------------------- launcher
extern "C" void kernel_launch(void* const* d_in, const int* in_sizes, int n_in,
                              void* d_out, int out_size) {
    const float* x  = (const float*)d_in[0];   // [128,128,170,12] f32
    const float* Es = (const float*)d_in[1];   // [128,170] f32
    float* out = (float*)d_out;                // [170,170] f32

    cudaFuncSetAttribute(k_gemm1, cudaFuncAttributeMaxDynamicSharedMemorySize, SMEM_G1);
    cudaFuncSetAttribute(k_adj,   cudaFuncAttributeMaxDynamicSharedMemorySize, SMEM_A);

    k_load<<<1184, 256>>>(x);
    dim3 g1(BATCH, 2);
    k_gemm1<<<g1, 256, SMEM_G1>>>(Es);
    k_adj<<<BATCH, 512, SMEM_A>>>();
    k_thresh<<<(NN * NN + 255) / 256, 256>>>(out);
}

// round 13
// speedup vs baseline: 1.0097x; 1.0097x over previous
#include <cuda_runtime.h>
#include <cuda_bf16.h>
#include <cstdint>

#define BATCH 128
#define CH    128
#define TTNN  2785280      // BATCH*CH*NN elements
#define NN    170
#define TT    12
#define NP    176          // padded node pitch
#define SCP   172          // score smem pitch (bf16)

static __device__ __align__(16) float    g_xs[BATCH * CH * NP];        // t-reduced x
static __device__ __align__(16) unsigned g_EdB[BATCH * NN * (NP/2)];   // E_d^T bf16 pairs
static __device__ float g_Asum[NN * NN];

// k_gemm1 smem: esB u32 [64][176] (45056 B) + xsP u64 [64][90] (46080 B)
#define SMEM_G1 (45056 + 46080)                        // 91,136 B -> 2 CTA/SM
// k_adj smem: ed f32 [170][176] + sc bf16 [170][172]
#define SMEM_A  (NN * NP * 4 + NN * SCP * 2)           // 178,160 B

// ------------------------------------------------------- packed f32x2 helpers
typedef unsigned long long u64t;

__device__ __forceinline__ u64t splat2(float v) {
    u64t d; asm("mov.b64 %0, {%1, %1};" : "=l"(d) : "f"(v)); return d;
}
__device__ __forceinline__ u64t mkpair_u(unsigned lo, unsigned hi) {
    u64t d; asm("mov.b64 %0, {%1, %2};" : "=l"(d) : "r"(lo), "r"(hi)); return d;
}
__device__ __forceinline__ void ffma2(u64t& c, u64t a, u64t b) {
    asm("fma.rn.f32x2 %0, %1, %2, %3;" : "=l"(c) : "l"(a), "l"(b), "l"(c));
}
__device__ __forceinline__ void unpack2(float& lo, float& hi, u64t v) {
    asm("mov.b64 {%0, %1}, %2;" : "=f"(lo), "=f"(hi) : "l"(v));
}
__device__ __forceinline__ float tanh_ap(float x) {
    float r; asm("tanh.approx.f32 %0, %1;" : "=f"(r) : "f"(x)); return r;
}
__device__ __forceinline__ float bf_lo(unsigned w) { return __uint_as_float(w << 16); }
__device__ __forceinline__ float bf_hi(unsigned w) { return __uint_as_float(w & 0xFFFF0000u); }
__device__ __forceinline__ unsigned bf_pack(float a, float b) {
    __nv_bfloat162 h = __floats2bfloat162_rn(a, b);
    return *reinterpret_cast<unsigned*>(&h);
}
__device__ __forceinline__ float f4sum(float4 v) {
    return (v.x + v.y) + (v.z + v.w);
}

// ---------------- K_load: staged coalesced t-reduction x -> g_xs   (R9 proven)
__global__ void __launch_bounds__(256) k_load(const float* __restrict__ x) {
    __shared__ float4 st[768];
    const int tid = threadIdx.x;

    // zero the pad columns of g_xs (np in [170,176))
    for (int i = blockIdx.x * 256 + tid; i < BATCH * CH * 6; i += gridDim.x * 256) {
        int bc = i / 6, j = i - bc * 6;
        g_xs[(size_t)bc * NP + NN + j] = 0.0f;
    }

    const int nchunks = TTNN / 256;                    // 10880 exactly
    const float4* xf4 = reinterpret_cast<const float4*>(x);
    for (int ch = blockIdx.x; ch < nchunks; ch += gridDim.x) {
        size_t base = (size_t)ch * 768;
        st[tid]       = __ldcs(xf4 + base + tid);
        st[tid + 256] = __ldcs(xf4 + base + tid + 256);
        st[tid + 512] = __ldcs(xf4 + base + tid + 512);
        __syncthreads();
        const float4* p = reinterpret_cast<const float4*>(
            reinterpret_cast<const float*>(st) + tid * TT);
        float4 v0 = p[0], v1 = p[1], v2 = p[2];
        float s = f4sum(v0) + f4sum(v1) + f4sum(v2);
        int e = ch * 256 + tid;
        int bc = e / NN, n = e - bc * NN;
        g_xs[(size_t)bc * NP + n] = s;
        __syncthreads();
    }
}

// ------ K_gemm1: c-pair scheme. acc lanes hold even/odd-c partial sums.
// ed[m][n] = tanh(sum_c Es[c][m] * xs[c][n]); cells 4m x 8n, 484 cells/CTA.
__global__ void __launch_bounds__(256, 2) k_gemm1(const float* __restrict__ Es) {
    extern __shared__ float smf[];
    unsigned* esB = reinterpret_cast<unsigned*>(smf);          // [c2=64][m=176] bf16x2
    unsigned* xsU = reinterpret_cast<unsigned*>(smf) + 64*176; // xsP as u32 [c2][n*2]
    u64t* xsP = reinterpret_cast<u64t*>(xsU);                  // [c2=64][n=90] f32x2
    const int tid = threadIdx.x;
    const int b = blockIdx.x, h = blockIdx.y;

    // stage Es: esB[c2][m] = bf16x2{Es[2c2][m], Es[2c2+1][m]} (coalesced along m)
    for (int i = tid; i < 64 * 176; i += 256) {
        int c2 = i / 176, m = i - c2 * 176;
        float f0 = 0.f, f1 = 0.f;
        if (m < NN) {
            f0 = Es[(2 * c2) * NN + m];
            f1 = Es[(2 * c2 + 1) * NN + m];
        }
        esB[i] = bf_pack(f0, f1);
    }
    // stage xs half transposed to c-pairs: xsP[c2][n] = {xs[2c2][n], xs[2c2+1][n]}
    {
        const float* src = g_xs + (size_t)b * CH * NP + 88 * h;
        for (int i = tid; i < CH * 88; i += 256) {
            int c = i / 88, n = i - c * 88;
            float v = src[(size_t)c * NP + n];          // coalesced global read
            xsU[(c >> 1) * 180 + n * 2 + (c & 1)] = __float_as_uint(v);
        }
        // zero pad n=88,89 of each c2 row (never read, but keep deterministic)
        for (int i = tid; i < 64 * 4; i += 256) {
            int c2 = i >> 2, j = i & 3;
            xsU[c2 * 180 + 176 + j] = 0u;
        }
    }
    __syncthreads();

    // 44 m-strips(4) x 11 n-strips(8) = 484 cells; threads take tid and tid+256
    for (int cell = tid; cell < 484; cell += 256) {
        const int smi = cell % 44, snj = cell / 44;
        const int am = smi * 4, bn = snj * 8;           // bn: u64 index = n
        u64t acc[4][8];
        #pragma unroll
        for (int i = 0; i < 4; i++)
            #pragma unroll
            for (int j = 0; j < 8; j++) acc[i][j] = 0ull;

        const unsigned* ep = esB + am;
        const u64t* bp = xsP + bn;
        #pragma unroll 2
        for (int c2 = 0; c2 < 64; c2++) {
            uint4 ev = *reinterpret_cast<const uint4*>(ep + c2 * 176);
            const ulonglong2* xq = reinterpret_cast<const ulonglong2*>(bp + c2 * 90);
            ulonglong2 x01 = xq[0], x23 = xq[1], x45 = xq[2], x67 = xq[3];
            unsigned ew[4] = {ev.x, ev.y, ev.z, ev.w};
            #pragma unroll
            for (int mi = 0; mi < 4; mi++) {
                u64t a = mkpair_u(ew[mi] << 16, ew[mi] & 0xFFFF0000u);
                ffma2(acc[mi][0], a, x01.x); ffma2(acc[mi][1], a, x01.y);
                ffma2(acc[mi][2], a, x23.x); ffma2(acc[mi][3], a, x23.y);
                ffma2(acc[mi][4], a, x45.x); ffma2(acc[mi][5], a, x45.y);
                ffma2(acc[mi][6], a, x67.x); ffma2(acc[mi][7], a, x67.y);
            }
        }

        // epilogue: fold lanes, tanh, pack bf16 pairs along n -> g_EdB
        #pragma unroll
        for (int mi = 0; mi < 4; mi++) {
            int m = am + mi;
            if (m < NN) {
                float f[8];
                #pragma unroll
                for (int j = 0; j < 8; j++) {
                    float lo, hi;
                    unpack2(lo, hi, acc[mi][j]);
                    f[j] = lo + hi;
                }
                uint4 o;
                o.x = bf_pack(tanh_ap(f[0]), tanh_ap(f[1]));
                o.y = bf_pack(tanh_ap(f[2]), tanh_ap(f[3]));
                o.z = bf_pack(tanh_ap(f[4]), tanh_ap(f[5]));
                o.w = bf_pack(tanh_ap(f[6]), tanh_ap(f[7]));
                unsigned* dst = g_EdB + ((size_t)b * NN + m) * (NP/2) + 44 * h + snj * 4;
                *reinterpret_cast<uint4*>(dst) = o;
            }
        }
    }
}

// -------- K_adj: symmetric GEMM2 (8x8 triangle) + softmax + atomic accumulate
__global__ void __launch_bounds__(512, 1) k_adj() {
    extern __shared__ float sm[];
    float* ed = sm;                                          // [170][176] f32
    __nv_bfloat16* sc = reinterpret_cast<__nv_bfloat16*>(sm + NN * NP);
    const int tid = threadIdx.x;
    const int b = blockIdx.x;

    // copy-in: bf16 -> f32 expansion
    {
        const uint4* src = reinterpret_cast<const uint4*>(g_EdB + (size_t)b * NN * (NP/2));
        for (int i = tid; i < (NN * NP) / 8; i += 512) {
            uint4 v = src[i];
            float4 f0, f1;
            f0.x = bf_lo(v.x); f0.y = bf_hi(v.x); f0.z = bf_lo(v.y); f0.w = bf_hi(v.y);
            f1.x = bf_lo(v.z); f1.y = bf_hi(v.z); f1.z = bf_lo(v.w); f1.w = bf_hi(v.w);
            reinterpret_cast<float4*>(ed)[2*i]   = f0;
            reinterpret_cast<float4*>(ed)[2*i+1] = f1;
        }
    }
    __syncthreads();

    const float scale = 0.08838834764831843f;                // 1/sqrt(128)
    const int cell = tid;
    if (cell < 253) {
        int si = (int)((sqrtf(8.0f * (float)cell + 1.0f) - 1.0f) * 0.5f);
        while ((si + 1) * (si + 2) / 2 <= cell) si++;
        while (si * (si + 1) / 2 > cell) si--;
        const int sj = cell - si * (si + 1) / 2;
        const int n = si * 8, k = sj * 8;

        u64t acc[8][4];
        #pragma unroll
        for (int i = 0; i < 8; i++)
            #pragma unroll
            for (int j = 0; j < 4; j++) acc[i][j] = 0ull;

        #pragma unroll 2
        for (int m = 0; m < NN; m++) {
            const float* row = ed + m * NP;
            ulonglong2 a01 = *reinterpret_cast<const ulonglong2*>(row + n);
            ulonglong2 a23 = *reinterpret_cast<const ulonglong2*>(row + n + 4);
            float4 k0 = *reinterpret_cast<const float4*>(row + k);
            float4 k1 = *reinterpret_cast<const float4*>(row + k + 4);
            float kv[8] = {k0.x, k0.y, k0.z, k0.w, k1.x, k1.y, k1.z, k1.w};
            #pragma unroll
            for (int ki = 0; ki < 8; ki++) {
                u64t s = splat2(kv[ki]);
                ffma2(acc[ki][0], s, a01.x); ffma2(acc[ki][1], s, a01.y);
                ffma2(acc[ki][2], s, a23.x); ffma2(acc[ki][3], s, a23.y);
            }
        }

        #pragma unroll
        for (int ki = 0; ki < 8; ki++) {
            int kk = k + ki;
            if (kk >= NN) continue;
            #pragma unroll
            for (int j = 0; j < 4; j++) {
                float v0, v1;
                unpack2(v0, v1, acc[ki][j]);
                int n0 = n + 2 * j, n1 = n0 + 1;
                __nv_bfloat16 h0 = __float2bfloat16(fmaxf(0.0f, v0 * scale));
                __nv_bfloat16 h1 = __float2bfloat16(fmaxf(0.0f, v1 * scale));
                if (n0 < NN) { sc[n0 * SCP + kk] = h0; sc[kk * SCP + n0] = h0; }
                if (n1 < NN) { sc[n1 * SCP + kk] = h1; sc[kk * SCP + n1] = h1; }
            }
        }
    }
    __syncthreads();

    // row softmax (scores in [0,~15.1] -> no max pass) + atomic accumulate
    const int wid = tid >> 5, lane = tid & 31;
    for (int n = wid; n < NN; n += 16) {
        const __nv_bfloat16* row = sc + n * SCP;
        float ssum = 0.0f;
        for (int kq = lane; kq < NN; kq += 32)
            ssum += __expf(__bfloat162float(row[kq]));
        #pragma unroll
        for (int o = 16; o; o >>= 1)
            ssum += __shfl_xor_sync(0xffffffffu, ssum, o);
        float inv = 1.0f / ssum;
        for (int kq = lane; kq < NN; kq += 32)
            atomicAdd(&g_Asum[n * NN + kq],
                      __expf(__bfloat162float(row[kq])) * inv);
    }
}

// --------------------------------- K_thresh: threshold + self-restore g_Asum
__global__ void k_thresh(float* __restrict__ out) {
    int i = blockIdx.x * blockDim.x + threadIdx.x;
    if (i < NN * NN) {
        out[i] = (g_Asum[i] > 64.0f) ? 1.0f : 0.0f;          // mean > 0.5
        g_Asum[i] = 0.0f;                                    // restore for replay
    }
}

// ------------------------------------------------------------------- launcher
extern "C" void kernel_launch(void* const* d_in, const int* in_sizes, int n_in,
                              void* d_out, int out_size) {
    const float* x  = (const float*)d_in[0];   // [128,128,170,12] f32
    const float* Es = (const float*)d_in[1];   // [128,170] f32
    float* out = (float*)d_out;                // [170,170] f32

    cudaFuncSetAttribute(k_gemm1, cudaFuncAttributeMaxDynamicSharedMemorySize, SMEM_G1);
    cudaFuncSetAttribute(k_adj,   cudaFuncAttributeMaxDynamicSharedMemorySize, SMEM_A);

    k_load<<<1184, 256>>>(x);
    dim3 g1(BATCH, 2);
    k_gemm1<<<g1, 256, SMEM_G1>>>(Es);
    k_adj<<<BATCH, 512, SMEM_A>>>();
    k_thresh<<<(NN * NN + 255) / 256, 256>>>(out);
}

// round 14
// speedup vs baseline: 1.1620x; 1.1508x over previous
#include <cuda_runtime.h>
#include <cuda_bf16.h>
#include <cstdint>

#define BATCH 128
#define CH    128
#define TTNN  2785280      // BATCH*CH*NN elements
#define NN    170
#define TT    12
#define NP    176          // padded node pitch
#define SCP   172          // score smem pitch (bf16)

static __device__ __align__(16) float g_xs[BATCH * CH * NP];   // t-reduced x
static __device__ float g_Asum[NN * NN];

// fused kernel smem:
//   phase 1: es u32 [128][88] @0 (45056 B) + xs f32 [128][176] @45056 (90112 B)
//   phase 2: ed f32 [176][176] @0 (123904 B) + sc bf16 [170][172] @123904 (58480 B)
#define SMEM_F 182384

// ------------------------------------------------------- packed f32x2 helpers
typedef unsigned long long u64t;

__device__ __forceinline__ u64t splat2(float v) {
    u64t d; asm("mov.b64 %0, {%1, %1};" : "=l"(d) : "f"(v)); return d;
}
__device__ __forceinline__ u64t splat2u(unsigned v) {
    u64t d; asm("mov.b64 %0, {%1, %1};" : "=l"(d) : "r"(v)); return d;
}
__device__ __forceinline__ void ffma2(u64t& c, u64t a, u64t b) {
    asm("fma.rn.f32x2 %0, %1, %2, %3;" : "=l"(c) : "l"(a), "l"(b), "l"(c));
}
__device__ __forceinline__ void unpack2(float& lo, float& hi, u64t v) {
    asm("mov.b64 {%0, %1}, %2;" : "=f"(lo), "=f"(hi) : "l"(v));
}
__device__ __forceinline__ float tanh_ap(float x) {
    float r; asm("tanh.approx.f32 %0, %1;" : "=f"(r) : "f"(x)); return r;
}
__device__ __forceinline__ unsigned bf_pack(float a, float b) {
    __nv_bfloat162 h = __floats2bfloat162_rn(a, b);
    return *reinterpret_cast<unsigned*>(&h);
}
__device__ __forceinline__ float f4sum(float4 v) {
    return (v.x + v.y) + (v.z + v.w);
}

// ---------------- K_load: staged coalesced t-reduction x -> g_xs   (R9 proven)
__global__ void __launch_bounds__(256) k_load(const float* __restrict__ x) {
    __shared__ float4 st[768];
    const int tid = threadIdx.x;

    // zero the pad columns of g_xs (np in [170,176))
    for (int i = blockIdx.x * 256 + tid; i < BATCH * CH * 6; i += gridDim.x * 256) {
        int bc = i / 6, j = i - bc * 6;
        g_xs[(size_t)bc * NP + NN + j] = 0.0f;
    }

    const int nchunks = TTNN / 256;                    // 10880 exactly
    const float4* xf4 = reinterpret_cast<const float4*>(x);
    for (int ch = blockIdx.x; ch < nchunks; ch += gridDim.x) {
        size_t base = (size_t)ch * 768;
        st[tid]       = __ldcs(xf4 + base + tid);
        st[tid + 256] = __ldcs(xf4 + base + tid + 256);
        st[tid + 512] = __ldcs(xf4 + base + tid + 512);
        __syncthreads();
        const float4* p = reinterpret_cast<const float4*>(
            reinterpret_cast<const float*>(st) + tid * TT);
        float4 v0 = p[0], v1 = p[1], v2 = p[2];
        float s = f4sum(v0) + f4sum(v1) + f4sum(v2);
        int e = ch * 256 + tid;
        int bc = e / NN, n = e - bc * NN;
        g_xs[(size_t)bc * NP + n] = s;
        __syncthreads();
    }
}

// ---- K_bg: fused GEMM1 (R9 scheme) + GEMM2 (R9 scheme) + softmax + atomics.
// One CTA per batch, 512 threads.
__global__ void __launch_bounds__(512, 1) k_bg(const float* __restrict__ Es) {
    extern __shared__ float smf[];
    unsigned* es = reinterpret_cast<unsigned*>(smf);         // [128][88] bf16x2
    float* xs = smf + 11264;                                 // [128][176] f32
    float* ed = smf;                                         // [176][176] f32 (phase 2)
    __nv_bfloat16* sc = reinterpret_cast<__nv_bfloat16*>(smf + 30976);
    const int tid = threadIdx.x;
    const int b = blockIdx.x;

    // ---- phase 1 staging
    // es[c][mp] = bf16x2{Es[c][2mp], Es[c][2mp+1]}, mp < 88 (m < 176, pad 0)
    for (int i = tid; i < CH * 88; i += 512) {
        int c = i / 88, mp = i - c * 88;
        int m0 = mp * 2;
        float f0 = 0.f, f1 = 0.f;
        if (m0 < NN) {
            float2 e = *reinterpret_cast<const float2*>(Es + c * NN + m0);
            f0 = e.x; f1 = e.y;
        }
        es[i] = bf_pack(f0, f1);
    }
    // xs: contiguous copy of this batch's [128][176] block (pads already 0)
    {
        const uint4* src = reinterpret_cast<const uint4*>(g_xs + (size_t)b * CH * NP);
        uint4* dst = reinterpret_cast<uint4*>(xs);
        for (int i = tid; i < (CH * NP) / 4; i += 512) dst[i] = src[i];
    }
    __syncthreads();

    // ---- GEMM1: ed[m][n] = tanh(sum_c Es[c][m]*xs[c][n]); 22x22 = 484 cells 8x8
    u64t acc[8][4];
    int am = 0, bn = 0;
    {
        const int cell = tid;
        #pragma unroll
        for (int i = 0; i < 8; i++)
            #pragma unroll
            for (int j = 0; j < 4; j++) acc[i][j] = 0ull;

        if (cell < 484) {
            const int smi = cell / 22, snj = cell - smi * 22;
            am = smi * 8; bn = snj * 8;
            const unsigned* ep = es + (am >> 1);
            const float* bp = xs + bn;
            #pragma unroll 2
            for (int c = 0; c < CH; c++) {
                uint4 ev = *reinterpret_cast<const uint4*>(ep + c * 88);
                ulonglong2 b01 = *reinterpret_cast<const ulonglong2*>(bp + c * NP);
                ulonglong2 b23 = *reinterpret_cast<const ulonglong2*>(bp + c * NP + 4);
                unsigned ew[4] = {ev.x, ev.y, ev.z, ev.w};
                #pragma unroll
                for (int q = 0; q < 4; q++) {
                    u64t s0 = splat2u(ew[q] << 16);
                    u64t s1 = splat2u(ew[q] & 0xFFFF0000u);
                    ffma2(acc[2*q][0], s0, b01.x);  ffma2(acc[2*q][1], s0, b01.y);
                    ffma2(acc[2*q][2], s0, b23.x);  ffma2(acc[2*q][3], s0, b23.y);
                    ffma2(acc[2*q+1][0], s1, b01.x); ffma2(acc[2*q+1][1], s1, b01.y);
                    ffma2(acc[2*q+1][2], s1, b23.x); ffma2(acc[2*q+1][3], s1, b23.y);
                }
            }
        }
    }
    __syncthreads();              // all reads of es/xs done -> ed may overlay

    // epilogue 1: tanh -> ed f32 [176][176] (full coverage, pad rows = 0)
    if (tid < 484) {
        #pragma unroll
        for (int mi = 0; mi < 8; mi++) {
            float f[8];
            #pragma unroll
            for (int j = 0; j < 4; j++) unpack2(f[2*j], f[2*j+1], acc[mi][j]);
            float4 lo, hi;
            lo.x = tanh_ap(f[0]); lo.y = tanh_ap(f[1]);
            lo.z = tanh_ap(f[2]); lo.w = tanh_ap(f[3]);
            hi.x = tanh_ap(f[4]); hi.y = tanh_ap(f[5]);
            hi.z = tanh_ap(f[6]); hi.w = tanh_ap(f[7]);
            float* dst = ed + (am + mi) * NP + bn;
            *reinterpret_cast<float4*>(dst) = lo;
            *reinterpret_cast<float4*>(dst + 4) = hi;
        }
    }
    __syncthreads();

    // ---- GEMM2: scores = relu(Ed@Ed^T/sqrt(C)); 8x8 triangle, 253 cells (R9)
    const float scale = 0.08838834764831843f;                // 1/sqrt(128)
    {
        const int cell = tid;
        if (cell < 253) {
            int si = (int)((sqrtf(8.0f * (float)cell + 1.0f) - 1.0f) * 0.5f);
            while ((si + 1) * (si + 2) / 2 <= cell) si++;
            while (si * (si + 1) / 2 > cell) si--;
            const int sj = cell - si * (si + 1) / 2;
            const int n = si * 8, k = sj * 8;

            #pragma unroll
            for (int i = 0; i < 8; i++)
                #pragma unroll
                for (int j = 0; j < 4; j++) acc[i][j] = 0ull;

            #pragma unroll 2
            for (int m = 0; m < NN; m++) {
                const float* row = ed + m * NP;
                ulonglong2 a01 = *reinterpret_cast<const ulonglong2*>(row + n);
                ulonglong2 a23 = *reinterpret_cast<const ulonglong2*>(row + n + 4);
                float4 k0 = *reinterpret_cast<const float4*>(row + k);
                float4 k1 = *reinterpret_cast<const float4*>(row + k + 4);
                float kv[8] = {k0.x, k0.y, k0.z, k0.w, k1.x, k1.y, k1.z, k1.w};
                #pragma unroll
                for (int ki = 0; ki < 8; ki++) {
                    u64t s = splat2(kv[ki]);
                    ffma2(acc[ki][0], s, a01.x); ffma2(acc[ki][1], s, a01.y);
                    ffma2(acc[ki][2], s, a23.x); ffma2(acc[ki][3], s, a23.y);
                }
            }

            #pragma unroll
            for (int ki = 0; ki < 8; ki++) {
                int kk = k + ki;
                if (kk >= NN) continue;
                #pragma unroll
                for (int j = 0; j < 4; j++) {
                    float v0, v1;
                    unpack2(v0, v1, acc[ki][j]);
                    int n0 = n + 2 * j, n1 = n0 + 1;
                    __nv_bfloat16 h0 = __float2bfloat16(fmaxf(0.0f, v0 * scale));
                    __nv_bfloat16 h1 = __float2bfloat16(fmaxf(0.0f, v1 * scale));
                    if (n0 < NN) { sc[n0 * SCP + kk] = h0; sc[kk * SCP + n0] = h0; }
                    if (n1 < NN) { sc[n1 * SCP + kk] = h1; sc[kk * SCP + n1] = h1; }
                }
            }
        }
    }
    __syncthreads();

    // ---- row softmax (scores in [0,~15.1] -> no max pass) + atomic accumulate
    const int wid = tid >> 5, lane = tid & 31;
    for (int n = wid; n < NN; n += 16) {
        const __nv_bfloat16* row = sc + n * SCP;
        float ssum = 0.0f;
        for (int kq = lane; kq < NN; kq += 32)
            ssum += __expf(__bfloat162float(row[kq]));
        #pragma unroll
        for (int o = 16; o; o >>= 1)
            ssum += __shfl_xor_sync(0xffffffffu, ssum, o);
        float inv = 1.0f / ssum;
        for (int kq = lane; kq < NN; kq += 32)
            atomicAdd(&g_Asum[n * NN + kq],
                      __expf(__bfloat162float(row[kq])) * inv);
    }
}

// --------------------------------- K_thresh: threshold + self-restore g_Asum
__global__ void k_thresh(float* __restrict__ out) {
    int i = blockIdx.x * blockDim.x + threadIdx.x;
    if (i < NN * NN) {
        out[i] = (g_Asum[i] > 64.0f) ? 1.0f : 0.0f;          // mean > 0.5
        g_Asum[i] = 0.0f;                                    // restore for replay
    }
}

// ------------------------------------------------------------------- launcher
extern "C" void kernel_launch(void* const* d_in, const int* in_sizes, int n_in,
                              void* d_out, int out_size) {
    const float* x  = (const float*)d_in[0];   // [128,128,170,12] f32
    const float* Es = (const float*)d_in[1];   // [128,170] f32
    float* out = (float*)d_out;                // [170,170] f32

    cudaFuncSetAttribute(k_bg, cudaFuncAttributeMaxDynamicSharedMemorySize, SMEM_F);

    k_load<<<1184, 256>>>(x);
    k_bg<<<BATCH, 512, SMEM_F>>>(Es);
    k_thresh<<<(NN * NN + 255) / 256, 256>>>(out);
}

// round 15
// speedup vs baseline: 1.2078x; 1.0395x over previous
#include <cuda_runtime.h>
#include <cuda_bf16.h>
#include <cstdint>

#define BATCH 128
#define CH    128
#define TTNN  2785280      // BATCH*CH*NN elements
#define NN    170
#define TT    12
#define NP    176          // padded node pitch
#define SCP   172          // score smem pitch (bf16)
#define AP    172          // g_Asum pitch (f32) -> 16B-aligned v4 groups

static __device__ __align__(16) float g_xs[BATCH * CH * NP];   // t-reduced x
static __device__ __align__(16) float g_Asum[NN * AP];         // padded accumulator

// fused kernel smem:
//   phase 1: es u32 [128][88] @0 (45056 B) + xs f32 [128][176] @45056 (90112 B)
//   phase 2: ed f32 [176][176] @0 (123904 B) + sc bf16 [170][172] @123904 (58480 B)
#define SMEM_F 182384

// ------------------------------------------------------- packed f32x2 helpers
typedef unsigned long long u64t;

__device__ __forceinline__ u64t splat2(float v) {
    u64t d; asm("mov.b64 %0, {%1, %1};" : "=l"(d) : "f"(v)); return d;
}
__device__ __forceinline__ u64t splat2u(unsigned v) {
    u64t d; asm("mov.b64 %0, {%1, %1};" : "=l"(d) : "r"(v)); return d;
}
__device__ __forceinline__ void ffma2(u64t& c, u64t a, u64t b) {
    asm("fma.rn.f32x2 %0, %1, %2, %3;" : "=l"(c) : "l"(a), "l"(b), "l"(c));
}
__device__ __forceinline__ void unpack2(float& lo, float& hi, u64t v) {
    asm("mov.b64 {%0, %1}, %2;" : "=f"(lo), "=f"(hi) : "l"(v));
}
__device__ __forceinline__ float tanh_ap(float x) {
    float r; asm("tanh.approx.f32 %0, %1;" : "=f"(r) : "f"(x)); return r;
}
__device__ __forceinline__ float bf_lo(unsigned w) { return __uint_as_float(w << 16); }
__device__ __forceinline__ float bf_hi(unsigned w) { return __uint_as_float(w & 0xFFFF0000u); }
__device__ __forceinline__ unsigned bf_pack(float a, float b) {
    __nv_bfloat162 h = __floats2bfloat162_rn(a, b);
    return *reinterpret_cast<unsigned*>(&h);
}
__device__ __forceinline__ float f4sum(float4 v) {
    return (v.x + v.y) + (v.z + v.w);
}
__device__ __forceinline__ void red4(float* a, float x, float y, float z, float w) {
    asm volatile("red.global.add.v4.f32 [%0], {%1, %2, %3, %4};"
                 :: "l"(a), "f"(x), "f"(y), "f"(z), "f"(w) : "memory");
}

// ---------------- K_load: staged coalesced t-reduction x -> g_xs   (R9 proven)
__global__ void __launch_bounds__(256) k_load(const float* __restrict__ x) {
    __shared__ float4 st[768];
    const int tid = threadIdx.x;

    // zero the pad columns of g_xs (np in [170,176))
    for (int i = blockIdx.x * 256 + tid; i < BATCH * CH * 6; i += gridDim.x * 256) {
        int bc = i / 6, j = i - bc * 6;
        g_xs[(size_t)bc * NP + NN + j] = 0.0f;
    }

    const int nchunks = TTNN / 256;                    // 10880 exactly
    const float4* xf4 = reinterpret_cast<const float4*>(x);
    for (int ch = blockIdx.x; ch < nchunks; ch += gridDim.x) {
        size_t base = (size_t)ch * 768;
        st[tid]       = __ldcs(xf4 + base + tid);
        st[tid + 256] = __ldcs(xf4 + base + tid + 256);
        st[tid + 512] = __ldcs(xf4 + base + tid + 512);
        __syncthreads();
        const float4* p = reinterpret_cast<const float4*>(
            reinterpret_cast<const float*>(st) + tid * TT);
        float4 v0 = p[0], v1 = p[1], v2 = p[2];
        float s = f4sum(v0) + f4sum(v1) + f4sum(v2);
        int e = ch * 256 + tid;
        int bc = e / NN, n = e - bc * NN;
        g_xs[(size_t)bc * NP + n] = s;
        __syncthreads();
    }
}

// ---- K_bg: fused GEMM1 + GEMM2 + softmax + vectorized reduction epilogue.
__global__ void __launch_bounds__(512, 1) k_bg(const float* __restrict__ Es) {
    extern __shared__ float smf[];
    unsigned* es = reinterpret_cast<unsigned*>(smf);         // [128][88] bf16x2
    float* xs = smf + 11264;                                 // [128][176] f32
    float* ed = smf;                                         // [176][176] f32 (phase 2)
    __nv_bfloat16* sc = reinterpret_cast<__nv_bfloat16*>(smf + 30976);
    const int tid = threadIdx.x;
    const int b = blockIdx.x;

    // ---- phase 1 staging
    for (int i = tid; i < CH * 88; i += 512) {
        int c = i / 88, mp = i - c * 88;
        int m0 = mp * 2;
        float f0 = 0.f, f1 = 0.f;
        if (m0 < NN) {
            float2 e = *reinterpret_cast<const float2*>(Es + c * NN + m0);
            f0 = e.x; f1 = e.y;
        }
        es[i] = bf_pack(f0, f1);
    }
    {
        const uint4* src = reinterpret_cast<const uint4*>(g_xs + (size_t)b * CH * NP);
        uint4* dst = reinterpret_cast<uint4*>(xs);
        for (int i = tid; i < (CH * NP) / 4; i += 512) dst[i] = src[i];
    }
    __syncthreads();

    // ---- GEMM1: ed[m][n] = tanh(sum_c Es[c][m]*xs[c][n]); 484 cells of 8x8
    u64t acc[8][4];
    int am = 0, bn = 0;
    {
        const int cell = tid;
        #pragma unroll
        for (int i = 0; i < 8; i++)
            #pragma unroll
            for (int j = 0; j < 4; j++) acc[i][j] = 0ull;

        if (cell < 484) {
            const int smi = cell / 22, snj = cell - smi * 22;
            am = smi * 8; bn = snj * 8;
            const unsigned* ep = es + (am >> 1);
            const float* bp = xs + bn;
            #pragma unroll 2
            for (int c = 0; c < CH; c++) {
                uint4 ev = *reinterpret_cast<const uint4*>(ep + c * 88);
                ulonglong2 b01 = *reinterpret_cast<const ulonglong2*>(bp + c * NP);
                ulonglong2 b23 = *reinterpret_cast<const ulonglong2*>(bp + c * NP + 4);
                unsigned ew[4] = {ev.x, ev.y, ev.z, ev.w};
                #pragma unroll
                for (int q = 0; q < 4; q++) {
                    u64t s0 = splat2u(ew[q] << 16);
                    u64t s1 = splat2u(ew[q] & 0xFFFF0000u);
                    ffma2(acc[2*q][0], s0, b01.x);  ffma2(acc[2*q][1], s0, b01.y);
                    ffma2(acc[2*q][2], s0, b23.x);  ffma2(acc[2*q][3], s0, b23.y);
                    ffma2(acc[2*q+1][0], s1, b01.x); ffma2(acc[2*q+1][1], s1, b01.y);
                    ffma2(acc[2*q+1][2], s1, b23.x); ffma2(acc[2*q+1][3], s1, b23.y);
                }
            }
        }
    }
    __syncthreads();              // all reads of es/xs done -> ed may overlay

    // epilogue 1: tanh -> ed f32 [176][176]
    if (tid < 484) {
        #pragma unroll
        for (int mi = 0; mi < 8; mi++) {
            float f[8];
            #pragma unroll
            for (int j = 0; j < 4; j++) unpack2(f[2*j], f[2*j+1], acc[mi][j]);
            float4 lo, hi;
            lo.x = tanh_ap(f[0]); lo.y = tanh_ap(f[1]);
            lo.z = tanh_ap(f[2]); lo.w = tanh_ap(f[3]);
            hi.x = tanh_ap(f[4]); hi.y = tanh_ap(f[5]);
            hi.z = tanh_ap(f[6]); hi.w = tanh_ap(f[7]);
            float* dst = ed + (am + mi) * NP + bn;
            *reinterpret_cast<float4*>(dst) = lo;
            *reinterpret_cast<float4*>(dst + 4) = hi;
        }
    }
    __syncthreads();

    // ---- GEMM2: scores = relu(Ed@Ed^T/sqrt(C)); 8x8 triangle, 253 cells
    const float scale = 0.08838834764831843f;                // 1/sqrt(128)
    {
        const int cell = tid;
        if (cell < 253) {
            int si = (int)((sqrtf(8.0f * (float)cell + 1.0f) - 1.0f) * 0.5f);
            while ((si + 1) * (si + 2) / 2 <= cell) si++;
            while (si * (si + 1) / 2 > cell) si--;
            const int sj = cell - si * (si + 1) / 2;
            const int n = si * 8, k = sj * 8;

            #pragma unroll
            for (int i = 0; i < 8; i++)
                #pragma unroll
                for (int j = 0; j < 4; j++) acc[i][j] = 0ull;

            #pragma unroll 2
            for (int m = 0; m < NN; m++) {
                const float* row = ed + m * NP;
                ulonglong2 a01 = *reinterpret_cast<const ulonglong2*>(row + n);
                ulonglong2 a23 = *reinterpret_cast<const ulonglong2*>(row + n + 4);
                float4 k0 = *reinterpret_cast<const float4*>(row + k);
                float4 k1 = *reinterpret_cast<const float4*>(row + k + 4);
                float kv[8] = {k0.x, k0.y, k0.z, k0.w, k1.x, k1.y, k1.z, k1.w};
                #pragma unroll
                for (int ki = 0; ki < 8; ki++) {
                    u64t s = splat2(kv[ki]);
                    ffma2(acc[ki][0], s, a01.x); ffma2(acc[ki][1], s, a01.y);
                    ffma2(acc[ki][2], s, a23.x); ffma2(acc[ki][3], s, a23.y);
                }
            }

            #pragma unroll
            for (int ki = 0; ki < 8; ki++) {
                int kk = k + ki;
                if (kk >= NN) continue;
                #pragma unroll
                for (int j = 0; j < 4; j++) {
                    float v0, v1;
                    unpack2(v0, v1, acc[ki][j]);
                    int n0 = n + 2 * j, n1 = n0 + 1;
                    __nv_bfloat16 h0 = __float2bfloat16(fmaxf(0.0f, v0 * scale));
                    __nv_bfloat16 h1 = __float2bfloat16(fmaxf(0.0f, v1 * scale));
                    if (n0 < NN) { sc[n0 * SCP + kk] = h0; sc[kk * SCP + n0] = h0; }
                    if (n1 < NN) { sc[n1 * SCP + kk] = h1; sc[kk * SCP + n1] = h1; }
                }
            }
        }
    }
    // zero sc pad columns (k = 170, 171) so u64 row loads are well-defined
    for (int i = tid; i < NN * 2; i += 512)
        sc[(i >> 1) * SCP + NN + (i & 1)] = __float2bfloat16(0.0f);
    __syncthreads();

    // ---- row softmax: single-exp, 4-wide groups, red.v4 accumulate
    const int wid = tid >> 5, lane = tid & 31;
    for (int n = wid; n < NN; n += 16) {
        const u64t* row64 = reinterpret_cast<const u64t*>(sc + n * SCP);  // 43 groups
        float e[8];
        float ssum = 0.0f;
        #pragma unroll
        for (int t = 0; t < 2; t++) {
            int g = lane + t * 32;
            if (g < 43) {
                u64t w = row64[g];
                unsigned lo = (unsigned)w, hi = (unsigned)(w >> 32);
                e[4*t+0] = __expf(bf_lo(lo));
                e[4*t+1] = __expf(bf_hi(lo));
                e[4*t+2] = (g == 42) ? 0.0f : __expf(bf_lo(hi));   // k=170 pad
                e[4*t+3] = (g == 42) ? 0.0f : __expf(bf_hi(hi));   // k=171 pad
                ssum += (e[4*t+0] + e[4*t+1]) + (e[4*t+2] + e[4*t+3]);
            } else {
                e[4*t+0] = e[4*t+1] = e[4*t+2] = e[4*t+3] = 0.0f;
            }
        }
        #pragma unroll
        for (int o = 16; o; o >>= 1)
            ssum += __shfl_xor_sync(0xffffffffu, ssum, o);
        float inv = 1.0f / ssum;
        #pragma unroll
        for (int t = 0; t < 2; t++) {
            int g = lane + t * 32;
            if (g < 43)
                red4(g_Asum + n * AP + 4 * g,
                     e[4*t+0] * inv, e[4*t+1] * inv, e[4*t+2] * inv, e[4*t+3] * inv);
        }
    }
}

// --------------------------------- K_thresh: threshold + self-restore g_Asum
__global__ void k_thresh(float* __restrict__ out) {
    int i = blockIdx.x * blockDim.x + threadIdx.x;
    if (i < NN * AP) {
        int n = i / AP, k = i - n * AP;
        float v = g_Asum[i];
        if (k < NN)
            out[n * NN + k] = (v > 64.0f) ? 1.0f : 0.0f;     // mean > 0.5
        g_Asum[i] = 0.0f;                                    // restore for replay
    }
}

// ------------------------------------------------------------------- launcher
extern "C" void kernel_launch(void* const* d_in, const int* in_sizes, int n_in,
                              void* d_out, int out_size) {
    const float* x  = (const float*)d_in[0];   // [128,128,170,12] f32
    const float* Es = (const float*)d_in[1];   // [128,170] f32
    float* out = (float*)d_out;                // [170,170] f32

    cudaFuncSetAttribute(k_bg, cudaFuncAttributeMaxDynamicSharedMemorySize, SMEM_F);

    k_load<<<1184, 256>>>(x);
    k_bg<<<BATCH, 512, SMEM_F>>>(Es);
    k_thresh<<<(NN * AP + 255) / 256, 256>>>(out);
}

// round 16
// speedup vs baseline: 1.3429x; 1.1119x over previous
#include <cuda_runtime.h>
#include <cuda_bf16.h>
#include <cstdint>

#define BATCH 128
#define CH    128
#define NN    170
#define TT    12
#define NP    176          // padded node pitch
#define SCP   172          // score smem pitch (bf16)
#define AP    172          // g_Asum pitch (f32)

static __device__ __align__(16) float g_Asum[NN * AP];

// k_all smem:
//   phase 1: es u32 [128][88] @0 (45056 B) + xs f32 [128][176] @45056 (90112 B)
//            + stage f4 [2040] @135168 (32640 B)  -> 167808 B
//   phase 2: ed f32 [176][176] @0 (123904 B) + sc bf16 [170][172] @123904 (58480 B)
#define SMEM_F 182384

// ------------------------------------------------------- packed f32x2 helpers
typedef unsigned long long u64t;

__device__ __forceinline__ u64t splat2(float v) {
    u64t d; asm("mov.b64 %0, {%1, %1};" : "=l"(d) : "f"(v)); return d;
}
__device__ __forceinline__ u64t splat2u(unsigned v) {
    u64t d; asm("mov.b64 %0, {%1, %1};" : "=l"(d) : "r"(v)); return d;
}
__device__ __forceinline__ void ffma2(u64t& c, u64t a, u64t b) {
    asm("fma.rn.f32x2 %0, %1, %2, %3;" : "=l"(c) : "l"(a), "l"(b), "l"(c));
}
__device__ __forceinline__ void unpack2(float& lo, float& hi, u64t v) {
    asm("mov.b64 {%0, %1}, %2;" : "=f"(lo), "=f"(hi) : "l"(v));
}
__device__ __forceinline__ float tanh_ap(float x) {
    float r; asm("tanh.approx.f32 %0, %1;" : "=f"(r) : "f"(x)); return r;
}
__device__ __forceinline__ float bf_lo(unsigned w) { return __uint_as_float(w << 16); }
__device__ __forceinline__ float bf_hi(unsigned w) { return __uint_as_float(w & 0xFFFF0000u); }
__device__ __forceinline__ unsigned bf_pack(float a, float b) {
    __nv_bfloat162 h = __floats2bfloat162_rn(a, b);
    return *reinterpret_cast<unsigned*>(&h);
}
__device__ __forceinline__ float f4sum(float4 v) {
    return (v.x + v.y) + (v.z + v.w);
}
__device__ __forceinline__ void red4(float* a, float x, float y, float z, float w) {
    asm volatile("red.global.add.v4.f32 [%0], {%1, %2, %3, %4};"
                 :: "l"(a), "f"(x), "f"(y), "f"(z), "f"(w) : "memory");
}

// ---- K_all: pipelined x-load + GEMM1 + GEMM2 + softmax (one CTA per batch)
__global__ void __launch_bounds__(512, 1) k_all(const float* __restrict__ x,
                                                const float* __restrict__ Es) {
    extern __shared__ float smf[];
    unsigned* es = reinterpret_cast<unsigned*>(smf);           // [128][88] bf16x2
    float* xs = smf + 11264;                                   // [128][176] f32
    float4* stage = reinterpret_cast<float4*>(smf + 33792);    // [2040] f4
    float* ed = smf;                                           // phase 2 overlay
    __nv_bfloat16* sc = reinterpret_cast<__nv_bfloat16*>(smf + 30976);
    const int tid = threadIdx.x;
    const int b = blockIdx.x;

    // ---- es staging: es[c][mp] = bf16x2{Es[c][2mp], Es[c][2mp+1]}
    for (int i = tid; i < CH * 88; i += 512) {
        int c = i / 88, mp = i - c * 88;
        int m0 = mp * 2;
        float f0 = 0.f, f1 = 0.f;
        if (m0 < NN) {
            float2 e = *reinterpret_cast<const float2*>(Es + c * NN + m0);
            f0 = e.x; f1 = e.y;
        }
        es[i] = bf_pack(f0, f1);
    }
    // zero xs pad columns (n in [170,176)) once
    for (int i = tid; i < CH * 6; i += 512) {
        int c = i / 6, j = i - c * 6;
        xs[c * NP + NN + j] = 0.0f;
    }

    // ---- GEMM1 cell setup (acc persists across all 32 groups)
    u64t acc[8][4];
    #pragma unroll
    for (int i = 0; i < 8; i++)
        #pragma unroll
        for (int j = 0; j < 4; j++) acc[i][j] = 0ull;
    const int cell = tid;
    const int smi = (cell < 484) ? cell / 22 : 0;
    const int snj = (cell < 484) ? cell - smi * 22 : 0;
    const int am = smi * 8, bn = snj * 8;
    const unsigned* ep0 = es + (am >> 1);
    const float* bp0 = xs + bn;

    // ---- prologue: LDG group 0 into regs (group = 4 channels = 2040 f4)
    const float4* xb4 = reinterpret_cast<const float4*>(
        x + (size_t)b * (CH * NN * TT));
    float4 r0, r1, r2, r3;
    r3 = make_float4(0.f, 0.f, 0.f, 0.f);
    r0 = __ldcs(xb4 + tid);
    r1 = __ldcs(xb4 + tid + 512);
    r2 = __ldcs(xb4 + tid + 1024);
    if (tid < 504) r3 = __ldcs(xb4 + tid + 1536);

    // ---- pipelined loop: 32 groups of 4 channels
    for (int g = 0; g < 32; g++) {
        // stage group g
        stage[tid]        = r0;
        stage[tid + 512]  = r1;
        stage[tid + 1024] = r2;
        if (tid < 504) stage[tid + 1536] = r3;
        __syncthreads();

        // prefetch group g+1 (completes during this group's GEMM)
        if (g < 31) {
            const float4* gn = xb4 + (size_t)(g + 1) * 2040;
            r0 = __ldcs(gn + tid);
            r1 = __ldcs(gn + tid + 512);
            r2 = __ldcs(gn + tid + 1024);
            if (tid < 504) r3 = __ldcs(gn + tid + 1536);
        }

        // t-reduce stage -> xs rows 4g..4g+3 (680 elements)
        {
            const float* stf = reinterpret_cast<const float*>(stage);
            {
                int e = tid;                       // 0..511
                const float4* p = reinterpret_cast<const float4*>(stf + e * TT);
                float4 v0 = p[0], v1 = p[1], v2 = p[2];
                int cl = e / NN, n = e - cl * NN;
                xs[(4 * g + cl) * NP + n] = f4sum(v0) + f4sum(v1) + f4sum(v2);
            }
            if (tid < 168) {
                int e = 512 + tid;                 // 512..679
                const float4* p = reinterpret_cast<const float4*>(stf + e * TT);
                float4 v0 = p[0], v1 = p[1], v2 = p[2];
                int cl = e / NN, n = e - cl * NN;
                xs[(4 * g + cl) * NP + n] = f4sum(v0) + f4sum(v1) + f4sum(v2);
            }
        }
        __syncthreads();

        // GEMM1 accumulate: c = 4g..4g+3 (R14-proven inner body)
        if (cell < 484) {
            #pragma unroll
            for (int cc = 0; cc < 4; cc++) {
                const int c = 4 * g + cc;
                uint4 ev = *reinterpret_cast<const uint4*>(ep0 + c * 88);
                ulonglong2 b01 = *reinterpret_cast<const ulonglong2*>(bp0 + c * NP);
                ulonglong2 b23 = *reinterpret_cast<const ulonglong2*>(bp0 + c * NP + 4);
                unsigned ew[4] = {ev.x, ev.y, ev.z, ev.w};
                #pragma unroll
                for (int q = 0; q < 4; q++) {
                    u64t s0 = splat2u(ew[q] << 16);
                    u64t s1 = splat2u(ew[q] & 0xFFFF0000u);
                    ffma2(acc[2*q][0], s0, b01.x);  ffma2(acc[2*q][1], s0, b01.y);
                    ffma2(acc[2*q][2], s0, b23.x);  ffma2(acc[2*q][3], s0, b23.y);
                    ffma2(acc[2*q+1][0], s1, b01.x); ffma2(acc[2*q+1][1], s1, b01.y);
                    ffma2(acc[2*q+1][2], s1, b23.x); ffma2(acc[2*q+1][3], s1, b23.y);
                }
            }
        }
    }
    __syncthreads();              // all reads of es/xs done -> ed may overlay

    // epilogue 1: tanh -> ed f32 [176][176]
    if (cell < 484) {
        #pragma unroll
        for (int mi = 0; mi < 8; mi++) {
            float f[8];
            #pragma unroll
            for (int j = 0; j < 4; j++) unpack2(f[2*j], f[2*j+1], acc[mi][j]);
            float4 lo, hi;
            lo.x = tanh_ap(f[0]); lo.y = tanh_ap(f[1]);
            lo.z = tanh_ap(f[2]); lo.w = tanh_ap(f[3]);
            hi.x = tanh_ap(f[4]); hi.y = tanh_ap(f[5]);
            hi.z = tanh_ap(f[6]); hi.w = tanh_ap(f[7]);
            float* dst = ed + (am + mi) * NP + bn;
            *reinterpret_cast<float4*>(dst) = lo;
            *reinterpret_cast<float4*>(dst + 4) = hi;
        }
    }
    __syncthreads();

    // ---- GEMM2: scores = relu(Ed@Ed^T/sqrt(C)); 8x8 triangle, 253 cells
    const float scale = 0.08838834764831843f;                // 1/sqrt(128)
    if (cell < 253) {
        int si = (int)((sqrtf(8.0f * (float)cell + 1.0f) - 1.0f) * 0.5f);
        while ((si + 1) * (si + 2) / 2 <= cell) si++;
        while (si * (si + 1) / 2 > cell) si--;
        const int sj = cell - si * (si + 1) / 2;
        const int n = si * 8, k = sj * 8;

        #pragma unroll
        for (int i = 0; i < 8; i++)
            #pragma unroll
            for (int j = 0; j < 4; j++) acc[i][j] = 0ull;

        #pragma unroll 2
        for (int m = 0; m < NN; m++) {
            const float* row = ed + m * NP;
            ulonglong2 a01 = *reinterpret_cast<const ulonglong2*>(row + n);
            ulonglong2 a23 = *reinterpret_cast<const ulonglong2*>(row + n + 4);
            float4 k0 = *reinterpret_cast<const float4*>(row + k);
            float4 k1 = *reinterpret_cast<const float4*>(row + k + 4);
            float kv[8] = {k0.x, k0.y, k0.z, k0.w, k1.x, k1.y, k1.z, k1.w};
            #pragma unroll
            for (int ki = 0; ki < 8; ki++) {
                u64t s = splat2(kv[ki]);
                ffma2(acc[ki][0], s, a01.x); ffma2(acc[ki][1], s, a01.y);
                ffma2(acc[ki][2], s, a23.x); ffma2(acc[ki][3], s, a23.y);
            }
        }

        #pragma unroll
        for (int ki = 0; ki < 8; ki++) {
            int kk = k + ki;
            if (kk >= NN) continue;
            #pragma unroll
            for (int j = 0; j < 4; j++) {
                float v0, v1;
                unpack2(v0, v1, acc[ki][j]);
                int n0 = n + 2 * j, n1 = n0 + 1;
                __nv_bfloat16 h0 = __float2bfloat16(fmaxf(0.0f, v0 * scale));
                __nv_bfloat16 h1 = __float2bfloat16(fmaxf(0.0f, v1 * scale));
                if (n0 < NN) { sc[n0 * SCP + kk] = h0; sc[kk * SCP + n0] = h0; }
                if (n1 < NN) { sc[n1 * SCP + kk] = h1; sc[kk * SCP + n1] = h1; }
            }
        }
    }
    // zero sc pad columns (k = 170, 171)
    for (int i = tid; i < NN * 2; i += 512)
        sc[(i >> 1) * SCP + NN + (i & 1)] = __float2bfloat16(0.0f);
    __syncthreads();

    // ---- row softmax: single-exp, 4-wide groups, red.v4 accumulate (R15)
    const int wid = tid >> 5, lane = tid & 31;
    for (int n = wid; n < NN; n += 16) {
        const u64t* row64 = reinterpret_cast<const u64t*>(sc + n * SCP);
        float e[8];
        float ssum = 0.0f;
        #pragma unroll
        for (int t = 0; t < 2; t++) {
            int g = lane + t * 32;
            if (g < 43) {
                u64t w = row64[g];
                unsigned lo = (unsigned)w, hi = (unsigned)(w >> 32);
                e[4*t+0] = __expf(bf_lo(lo));
                e[4*t+1] = __expf(bf_hi(lo));
                e[4*t+2] = (g == 42) ? 0.0f : __expf(bf_lo(hi));
                e[4*t+3] = (g == 42) ? 0.0f : __expf(bf_hi(hi));
                ssum += (e[4*t+0] + e[4*t+1]) + (e[4*t+2] + e[4*t+3]);
            } else {
                e[4*t+0] = e[4*t+1] = e[4*t+2] = e[4*t+3] = 0.0f;
            }
        }
        #pragma unroll
        for (int o = 16; o; o >>= 1)
            ssum += __shfl_xor_sync(0xffffffffu, ssum, o);
        float inv = 1.0f / ssum;
        #pragma unroll
        for (int t = 0; t < 2; t++) {
            int g = lane + t * 32;
            if (g < 43)
                red4(g_Asum + n * AP + 4 * g,
                     e[4*t+0] * inv, e[4*t+1] * inv, e[4*t+2] * inv, e[4*t+3] * inv);
        }
    }
}

// --------------------------------- K_thresh: threshold + self-restore g_Asum
__global__ void k_thresh(float* __restrict__ out) {
    int i = blockIdx.x * blockDim.x + threadIdx.x;
    if (i < NN * AP) {
        int n = i / AP, k = i - n * AP;
        float v = g_Asum[i];
        if (k < NN)
            out[n * NN + k] = (v > 64.0f) ? 1.0f : 0.0f;     // mean > 0.5
        g_Asum[i] = 0.0f;                                    // restore for replay
    }
}

// ------------------------------------------------------------------- launcher
extern "C" void kernel_launch(void* const* d_in, const int* in_sizes, int n_in,
                              void* d_out, int out_size) {
    const float* x  = (const float*)d_in[0];   // [128,128,170,12] f32
    const float* Es = (const float*)d_in[1];   // [128,170] f32
    float* out = (float*)d_out;                // [170,170] f32

    cudaFuncSetAttribute(k_all, cudaFuncAttributeMaxDynamicSharedMemorySize, SMEM_F);

    k_all<<<BATCH, 512, SMEM_F>>>(x, Es);
    k_thresh<<<(NN * AP + 255) / 256, 256>>>(out);
}

// round 17
// speedup vs baseline: 1.7804x; 1.3257x over previous
#include <cuda_runtime.h>
#include <cuda_bf16.h>
#include <cstdint>

#define BATCH 128
#define CH    128
#define TTNN  2785280      // BATCH*CH*NN elements
#define NN    170
#define TT    12
#define NP    176          // g_xs padded node pitch (f32)
#define SCP   172          // score smem pitch (bf16)
#define AP    172          // g_Asum pitch (f32)

#define ESP   136          // es_t pitch (bf16)  -> LDSM conflict-free
#define XSP2  184          // xs/ed pitch (bf16) -> LDSM conflict-free

static __device__ __align__(16) float g_xs[BATCH * CH * NP];
static __device__ __align__(16) float g_Asum[NN * AP];

// k_bg2 smem layout (bytes):
//   es_t bf16 [176][136] @ 0       : 47872
//   xs   bf16 [128][184] @ 47872   : 47104
//   ed   bf16 [176][184] @ 94976   : 64768
//   sc   bf16 [170][172] @ 159744  : 58480
#define OFF_XS 47872
#define OFF_ED 94976
#define OFF_SC 159744
#define SMEM_B 218224

typedef unsigned long long u64t;

__device__ __forceinline__ float tanh_ap(float x) {
    float r; asm("tanh.approx.f32 %0, %1;" : "=f"(r) : "f"(x)); return r;
}
__device__ __forceinline__ float bf_lo(unsigned w) { return __uint_as_float(w << 16); }
__device__ __forceinline__ float bf_hi(unsigned w) { return __uint_as_float(w & 0xFFFF0000u); }
__device__ __forceinline__ unsigned bf_pack(float a, float b) {
    __nv_bfloat162 h = __floats2bfloat162_rn(a, b);
    return *reinterpret_cast<unsigned*>(&h);
}
__device__ __forceinline__ float f4sum(float4 v) {
    return (v.x + v.y) + (v.z + v.w);
}
__device__ __forceinline__ void red4(float* a, float x, float y, float z, float w) {
    asm volatile("red.global.add.v4.f32 [%0], {%1, %2, %3, %4};"
                 :: "l"(a), "f"(x), "f"(y), "f"(z), "f"(w) : "memory");
}
__device__ __forceinline__ void ldsm4(unsigned& r0, unsigned& r1, unsigned& r2,
                                      unsigned& r3, unsigned a) {
    asm volatile("ldmatrix.sync.aligned.m8n8.x4.shared.b16 {%0,%1,%2,%3}, [%4];"
                 : "=r"(r0), "=r"(r1), "=r"(r2), "=r"(r3) : "r"(a));
}
__device__ __forceinline__ void ldsm4t(unsigned& r0, unsigned& r1, unsigned& r2,
                                       unsigned& r3, unsigned a) {
    asm volatile("ldmatrix.sync.aligned.m8n8.x4.trans.shared.b16 {%0,%1,%2,%3}, [%4];"
                 : "=r"(r0), "=r"(r1), "=r"(r2), "=r"(r3) : "r"(a));
}
__device__ __forceinline__ void ldsm2t(unsigned& r0, unsigned& r1, unsigned a) {
    asm volatile("ldmatrix.sync.aligned.m8n8.x2.trans.shared.b16 {%0,%1}, [%2];"
                 : "=r"(r0), "=r"(r1) : "r"(a));
}
__device__ __forceinline__ void mma16816(float d[4], unsigned a0, unsigned a1,
                                         unsigned a2, unsigned a3,
                                         unsigned b0, unsigned b1) {
    asm volatile(
        "mma.sync.aligned.m16n8k16.row.col.f32.bf16.bf16.f32 "
        "{%0,%1,%2,%3}, {%4,%5,%6,%7}, {%8,%9}, {%0,%1,%2,%3};"
        : "+f"(d[0]), "+f"(d[1]), "+f"(d[2]), "+f"(d[3])
        : "r"(a0), "r"(a1), "r"(a2), "r"(a3), "r"(b0), "r"(b1));
}

// ---------------- K_load: staged coalesced t-reduction x -> g_xs   (proven)
__global__ void __launch_bounds__(256) k_load(const float* __restrict__ x) {
    __shared__ float4 st[768];
    const int tid = threadIdx.x;
    for (int i = blockIdx.x * 256 + tid; i < BATCH * CH * 6; i += gridDim.x * 256) {
        int bc = i / 6, j = i - bc * 6;
        g_xs[(size_t)bc * NP + NN + j] = 0.0f;
    }
    const int nchunks = TTNN / 256;
    const float4* xf4 = reinterpret_cast<const float4*>(x);
    for (int ch = blockIdx.x; ch < nchunks; ch += gridDim.x) {
        size_t base = (size_t)ch * 768;
        st[tid]       = __ldcs(xf4 + base + tid);
        st[tid + 256] = __ldcs(xf4 + base + tid + 256);
        st[tid + 512] = __ldcs(xf4 + base + tid + 512);
        __syncthreads();
        const float4* p = reinterpret_cast<const float4*>(
            reinterpret_cast<const float*>(st) + tid * TT);
        float4 v0 = p[0], v1 = p[1], v2 = p[2];
        float s = f4sum(v0) + f4sum(v1) + f4sum(v2);
        int e = ch * 256 + tid;
        int bc = e / NN, n = e - bc * NN;
        g_xs[(size_t)bc * NP + n] = s;
        __syncthreads();
    }
}

// ---- K_bg2: HMMA GEMM1 + GEMM2 + softmax + red4 (one CTA per batch)
__global__ void __launch_bounds__(512, 1) k_bg2(const float* __restrict__ Es) {
    extern __shared__ char smc[];
    __nv_bfloat16* es_t = reinterpret_cast<__nv_bfloat16*>(smc);           // [176][136]
    __nv_bfloat16* xs   = reinterpret_cast<__nv_bfloat16*>(smc + OFF_XS);  // [128][184]
    __nv_bfloat16* ed   = reinterpret_cast<__nv_bfloat16*>(smc + OFF_ED);  // [176][184]
    __nv_bfloat16* sc   = reinterpret_cast<__nv_bfloat16*>(smc + OFF_SC);  // [170][172]
    const unsigned es_b = (unsigned)__cvta_generic_to_shared(es_t);
    const unsigned xs_b = (unsigned)__cvta_generic_to_shared(xs);
    const unsigned ed_b = (unsigned)__cvta_generic_to_shared(ed);
    const int tid = threadIdx.x;
    const int b = blockIdx.x;
    const int w = tid >> 5, l = tid & 31;

    // ---- staging
    for (int i = tid; i < CH * 176; i += 512) {           // es_t[m][c] = Es[c][m]
        int c = i / 176, m = i - c * 176;
        float v = (m < NN) ? Es[c * NN + m] : 0.0f;
        es_t[m * ESP + c] = __float2bfloat16(v);
    }
    {
        const float* src = g_xs + (size_t)b * CH * NP;
        for (int i = tid; i < CH * 176; i += 512) {        // xs[c][n] bf16
            int c = i / 176, n = i - c * 176;
            xs[c * XSP2 + n] = __float2bfloat16(src[c * NP + n]);
        }
    }
    __syncthreads();

    // ---- GEMM1: D1[m][n] = sum_c es_t[m][c] * xs[c][n]; 11x22 = 242 tiles m16n8
    {
        const int g2 = l >> 3, r8 = l & 7;
        const int arow_off = r8 + ((l >> 3) & 1) * 8;          // A lanes: +m0
        const int acol_off = (l >> 4) * 8;                     // +c0
        const int brl = l & 15;
        const int brow_off = (brl & 7) + ((brl >> 3) & 1) * 8; // B lanes: +c0
        (void)g2;
        for (int t = w; t < 242; t += 16) {
            const int m0 = (t / 22) * 16, n0 = (t - (t / 22) * 22) * 8;
            float d[4] = {0.f, 0.f, 0.f, 0.f};
            unsigned aaddr = es_b + ((m0 + arow_off) * ESP + acol_off) * 2;
            unsigned baddr = xs_b + (brow_off * XSP2 + n0) * 2;
            #pragma unroll
            for (int kk = 0; kk < 8; kk++) {
                unsigned a0, a1, a2, a3, b0, b1;
                ldsm4(a0, a1, a2, a3, aaddr + kk * 32);            // c0 += 16
                ldsm2t(b0, b1, baddr + kk * (16 * XSP2 * 2));
                mma16816(d, a0, a1, a2, a3, b0, b1);
            }
            // epilogue: tanh -> ed[m][n] bf16 pairs
            int row = m0 + (l >> 2), colp = n0 + 2 * (l & 3);
            *reinterpret_cast<unsigned*>(&ed[row * XSP2 + colp]) =
                bf_pack(tanh_ap(d[0]), tanh_ap(d[1]));
            *reinterpret_cast<unsigned*>(&ed[(row + 8) * XSP2 + colp]) =
                bf_pack(tanh_ap(d[2]), tanh_ap(d[3]));
        }
    }
    __syncthreads();

    // ---- GEMM2: D2[n][k] = sum_m ed[m][n]*ed[m][k]; triangle 132 tiles m16n8
    const float scale = 0.08838834764831843f;             // 1/sqrt(128)
    {
        const int g = l >> 3, r8 = l & 7;
        const int a_row_off = r8 + (g >> 1) * 8;           // ed row (+m0)
        const int a_col_sel = (g & 1) * 8;                 // ed col (+n0)
        const int brl = l & 15;
        const int brow_off = (brl & 7) + ((brl >> 3) & 1) * 8;
        for (int t = w; t < 132; t += 16) {
            int si = (int)((sqrtf(4.0f * (float)t + 1.0f) - 1.0f) * 0.5f);
            while ((si + 1) * (si + 2) <= t + si + 1) si++;   // (si+1)^2+(si+1) <= t
            while (si * si + si > t) si--;
            const int sj = t - si * si - si;
            const int n0 = si * 16, k0 = sj * 8;

            float d[4] = {0.f, 0.f, 0.f, 0.f};
            unsigned aaddr = ed_b + (a_row_off * XSP2 + n0 + a_col_sel) * 2;
            unsigned baddr = ed_b + (brow_off * XSP2 + k0) * 2;
            #pragma unroll
            for (int km = 0; km < 11; km++) {
                unsigned a0, a1, a2, a3, b0, b1;
                ldsm4t(a0, a1, a2, a3, aaddr + km * (16 * XSP2 * 2));
                ldsm2t(b0, b1, baddr + km * (16 * XSP2 * 2));
                mma16816(d, a0, a1, a2, a3, b0, b1);
            }
            // epilogue: relu/scale -> sc[n][k] + mirror sc[k][n]
            int n = n0 + (l >> 2), kp = k0 + 2 * (l & 3);
            float s0 = fmaxf(0.f, d[0] * scale), s1 = fmaxf(0.f, d[1] * scale);
            float s2 = fmaxf(0.f, d[2] * scale), s3 = fmaxf(0.f, d[3] * scale);
            if (kp < NN) {
                if (n < NN) {
                    *reinterpret_cast<unsigned*>(&sc[n * SCP + kp]) = bf_pack(s0, s1);
                    sc[kp * SCP + n] = __float2bfloat16(s0);
                    sc[(kp + 1) * SCP + n] = __float2bfloat16(s1);
                }
                if (n + 8 < NN) {
                    *reinterpret_cast<unsigned*>(&sc[(n + 8) * SCP + kp]) = bf_pack(s2, s3);
                    sc[kp * SCP + n + 8] = __float2bfloat16(s2);
                    sc[(kp + 1) * SCP + n + 8] = __float2bfloat16(s3);
                }
            }
        }
    }
    // zero sc pad columns (k = 170, 171)
    for (int i = tid; i < NN * 2; i += 512)
        sc[(i >> 1) * SCP + NN + (i & 1)] = __float2bfloat16(0.0f);
    __syncthreads();

    // ---- row softmax: single-exp, 4-wide groups, red.v4 accumulate (R15)
    const int wid = tid >> 5, lane = tid & 31;
    for (int n = wid; n < NN; n += 16) {
        const u64t* row64 = reinterpret_cast<const u64t*>(sc + n * SCP);
        float e[8];
        float ssum = 0.0f;
        #pragma unroll
        for (int t = 0; t < 2; t++) {
            int g = lane + t * 32;
            if (g < 43) {
                u64t wv = row64[g];
                unsigned lo = (unsigned)wv, hi = (unsigned)(wv >> 32);
                e[4*t+0] = __expf(bf_lo(lo));
                e[4*t+1] = __expf(bf_hi(lo));
                e[4*t+2] = (g == 42) ? 0.0f : __expf(bf_lo(hi));
                e[4*t+3] = (g == 42) ? 0.0f : __expf(bf_hi(hi));
                ssum += (e[4*t+0] + e[4*t+1]) + (e[4*t+2] + e[4*t+3]);
            } else {
                e[4*t+0] = e[4*t+1] = e[4*t+2] = e[4*t+3] = 0.0f;
            }
        }
        #pragma unroll
        for (int o = 16; o; o >>= 1)
            ssum += __shfl_xor_sync(0xffffffffu, ssum, o);
        float inv = 1.0f / ssum;
        #pragma unroll
        for (int t = 0; t < 2; t++) {
            int g = lane + t * 32;
            if (g < 43)
                red4(g_Asum + n * AP + 4 * g,
                     e[4*t+0] * inv, e[4*t+1] * inv, e[4*t+2] * inv, e[4*t+3] * inv);
        }
    }
}

// --------------------------------- K_thresh: threshold + self-restore g_Asum
__global__ void k_thresh(float* __restrict__ out) {
    int i = blockIdx.x * blockDim.x + threadIdx.x;
    if (i < NN * AP) {
        int n = i / AP, k = i - n * AP;
        float v = g_Asum[i];
        if (k < NN)
            out[n * NN + k] = (v > 64.0f) ? 1.0f : 0.0f;     // mean > 0.5
        g_Asum[i] = 0.0f;
    }
}

// ------------------------------------------------------------------- launcher
extern "C" void kernel_launch(void* const* d_in, const int* in_sizes, int n_in,
                              void* d_out, int out_size) {
    const float* x  = (const float*)d_in[0];   // [128,128,170,12] f32
    const float* Es = (const float*)d_in[1];   // [128,170] f32
    float* out = (float*)d_out;                // [170,170] f32

    cudaFuncSetAttribute(k_bg2, cudaFuncAttributeMaxDynamicSharedMemorySize, SMEM_B);

    k_load<<<1184, 256>>>(x);
    k_bg2<<<BATCH, 512, SMEM_B>>>(Es);
    k_thresh<<<(NN * AP + 255) / 256, 256>>>(out);
}